// round 16
// baseline (speedup 1.0000x reference)
#include <cuda_runtime.h>
#include <math.h>
#include <stdint.h>

#define NB 8
#define NPTS 16384
#define NS 1024
#define PC 256
#define R2 0.0625f
#define NPATCH (NB * NS)

// ---- precomputed W fragments (B-operand layout for mma.m16n8k16) ----
// index = (kt*32 + nt)*32 + lane ; {x,y,z,w} = {b0hi, b1hi, b0lo, b1lo}
__device__ uint4 W1frag[6 * 32 * 32];     // K padded 91 -> 96
__device__ uint4 W2frag[16 * 32 * 32];
// ---- precomputed X A-fragments: [patch][kt(6)][mt(2)][lane(32)] ----
__device__ uint4 XfragHi[(size_t)NPATCH * 12 * 32];
__device__ uint4 XfragLo[(size_t)NPATCH * 12 * 32];

__device__ __forceinline__ unsigned pack_bf16(float e0, float e1) {
    unsigned r;
    asm("cvt.rn.bf16x2.f32 %0, %1, %2;" : "=r"(r) : "f"(e1), "f"(e0));
    return r;   // low half = bf16(e0), high half = bf16(e1)
}
__device__ __forceinline__ void split2(float e0, float e1, unsigned &hi, unsigned &lo) {
    hi = pack_bf16(e0, e1);
    const float h0 = __uint_as_float(hi << 16);
    const float h1 = __uint_as_float(hi & 0xffff0000u);
    lo = pack_bf16(e0 - h0, e1 - h1);
}
__device__ __forceinline__ void mma16816(float* c, const unsigned* a,
                                         unsigned b0, unsigned b1) {
    asm("mma.sync.aligned.m16n8k16.row.col.f32.bf16.bf16.f32 "
        "{%0,%1,%2,%3}, {%4,%5,%6,%7}, {%8,%9}, {%0,%1,%2,%3};"
        : "+f"(c[0]), "+f"(c[1]), "+f"(c[2]), "+f"(c[3])
        : "r"(a[0]), "r"(a[1]), "r"(a[2]), "r"(a[3]), "r"(b0), "r"(b1));
}
__device__ __forceinline__ uint32_t smem_u32(const void* p) {
    uint32_t a;
    asm("{ .reg .u64 t; cvta.to.shared.u64 t, %1; cvt.u32.u64 %0, t; }"
        : "=r"(a) : "l"(p));
    return a;
}
__device__ __forceinline__ void cp16(uint32_t saddr, const void* gptr) {
    asm volatile("cp.async.ca.shared.global [%0], [%1], 16;"
                 :: "r"(saddr), "l"(gptr) : "memory");
}
#define CP_COMMIT() asm volatile("cp.async.commit_group;" ::: "memory")
#define CP_WAIT1()  asm volatile("cp.async.wait_group 1;" ::: "memory")
#define CP_WAIT0()  asm volatile("cp.async.wait_group 0;" ::: "memory")

// Abramowitz-Stegun 7.1.26 rational erf: |err| <= 1.5e-7, branch-free.
__device__ __forceinline__ float fast_erff(float x) {
    const float ax = fabsf(x);
    const float t = __fdividef(1.0f, fmaf(0.3275911f, ax, 1.0f));
    float p = fmaf(1.061405429f, t, -1.453152027f);
    p = fmaf(p, t, 1.421413741f);
    p = fmaf(p, t, -0.284496736f);
    p = fmaf(p, t, 0.254829592f);
    p *= t;
    const float e = __expf(-ax * ax);
    const float r = fmaf(-p, e, 1.0f);
    return copysignf(r, x);
}
__device__ __forceinline__ float gelu(float v) {
    return 0.5f * v * (1.0f + fast_erff(v * 0.70710678118654752440f));
}

// stage one nt-quad of B fragments into this warp's smem buffer st.
// Each lane stages exactly the 16B it will itself consume -> per-thread
// cp.async.wait is sufficient; NO barrier of any kind is needed.
__device__ __forceinline__ void stage_quad(uint32_t dstbase, const uint4* __restrict__ W,
                                           int kt, int q, int st, int w) {
    const uint4* src = W + kt * 1024 + w * 256 + q * 128;  // +lane folded in dstbase caller? no:
    // dstbase already includes lane*16; src needs +lane added by caller via pointer.
    (void)src;
}

// ---- prep: build W fragments (idempotent each launch) ----
__global__ void prep_kernel(const float* __restrict__ W1, const float* __restrict__ W2) {
    const int t = blockIdx.x * blockDim.x + threadIdx.x;
    if (t < 6144) {
        const int lane = t & 31, nt = (t >> 5) & 31, kt = t >> 10;
        const int k0 = kt * 16 + (lane & 3) * 2;
        const int n  = nt * 8 + (lane >> 2);
        const float e00 = (k0     < 91) ? W1[(k0    ) * PC + n] : 0.f;
        const float e01 = (k0 + 1 < 91) ? W1[(k0 + 1) * PC + n] : 0.f;
        const float e10 = (k0 + 8 < 91) ? W1[(k0 + 8) * PC + n] : 0.f;
        const float e11 = (k0 + 9 < 91) ? W1[(k0 + 9) * PC + n] : 0.f;
        uint4 v;
        split2(e00, e01, v.x, v.z);
        split2(e10, e11, v.y, v.w);
        W1frag[t] = v;
    } else if (t < 6144 + 16384) {
        const int u = t - 6144;
        const int lane = u & 31, nt = (u >> 5) & 31, kt = u >> 10;
        const int k0 = kt * 16 + (lane & 3) * 2;
        const int n  = nt * 8 + (lane >> 2);
        uint4 v;
        split2(W2[k0 * PC + n],       W2[(k0 + 1) * PC + n], v.x, v.z);
        split2(W2[(k0 + 8) * PC + n], W2[(k0 + 9) * PC + n], v.y, v.w);
        W2frag[u] = v;
    }
}

// ---- kernel A: ball query + gather + encode + A-fragment build ----
__global__ __launch_bounds__(128)
void group_kernel(const float* __restrict__ xyz, const float* __restrict__ feat,
                  const float* __restrict__ center, float* __restrict__ out)
{
    __shared__ float Xs[32][98];
    __shared__ int sc_idx[4][32];
    __shared__ int sc_cnt[4];
    __shared__ int gidx[32];

    const int bs   = blockIdx.x;
    const int b    = bs >> 10;
    const int tid  = threadIdx.x;
    const int w    = tid >> 5;
    const int lane = tid & 31;

    const float cx = center[bs * 3 + 0];
    const float cy = center[bs * 3 + 1];
    const float cz = center[bs * 3 + 2];
    const float cs = __fadd_rn(__fadd_rn(__fmul_rn(cx, cx), __fmul_rn(cy, cy)),
                               __fmul_rn(cz, cz));

    // ball query: 4 warps x 4096-point segments, first-32 kept
    {
        const float* xb = xyz + (size_t)b * NPTS * 3;
        int cnt = 0;
        const int base = w * 4096;
        for (int it = 0; it < 128; ++it) {
            const int n = base + it * 32 + lane;
            const float px = xb[n * 3 + 0];
            const float py = xb[n * 3 + 1];
            const float pz = xb[n * 3 + 2];
            const float ps = __fadd_rn(__fadd_rn(__fmul_rn(px, px), __fmul_rn(py, py)),
                                       __fmul_rn(pz, pz));
            const float dt = __fadd_rn(__fadd_rn(__fmul_rn(cx, px), __fmul_rn(cy, py)),
                                       __fmul_rn(cz, pz));
            const float sq = __fsub_rn(__fadd_rn(cs, ps), __fmul_rn(2.0f, dt));
            const bool hit = (sq <= R2);
            const unsigned m = __ballot_sync(0xffffffffu, hit);
            const int rank = __popc(m & ((1u << lane) - 1u));
            if (hit && (cnt + rank) < 32) sc_idx[w][cnt + rank] = n;
            cnt += __popc(m);
            if (cnt >= 32) break;
        }
        if (lane == 0) sc_cnt[w] = cnt < 32 ? cnt : 32;
    }
    __syncthreads();

    if (w == 0) {
        int val = NPTS, tot = 0;
        #pragma unroll
        for (int ww = 0; ww < 4; ++ww) {
            const int c = sc_cnt[ww];
            if (lane >= tot && lane < tot + c) val = sc_idx[ww][lane - tot];
            tot += c;
        }
        const int v0 = __shfl_sync(0xffffffffu, val, 0);
        if (val == NPTS) val = v0;
        gidx[lane] = val < (NPTS - 1) ? val : (NPTS - 1);
        out[(size_t)NPATCH * PC + (size_t)bs * 32 + lane] = (float)val;
    }
    __syncthreads();

    // gather + rel-pos encoding
    if (tid < 96) {
        const int k = tid / 3, d = tid - k * 3;
        const int gi = gidx[k];
        const float cd = (d == 0) ? cx : ((d == 1) ? cy : cz);
        Xs[k][64 + d] = xyz[((size_t)b * NPTS + gi) * 3 + d] - cd;
    }
    #pragma unroll
    for (int t = tid; t < 512; t += 128) {
        const int k = t >> 4, c = (t & 15) * 4;
        const float4 v = *(const float4*)&feat[((size_t)b * NPTS + gidx[k]) * 64 + c];
        Xs[k][c + 0] = v.x; Xs[k][c + 1] = v.y;
        Xs[k][c + 2] = v.z; Xs[k][c + 3] = v.w;
    }
    #pragma unroll
    for (int t = tid; t < 32 * 7; t += 128) {
        Xs[t / 7][91 + t % 7] = 0.f;
    }
    __syncthreads();
    #pragma unroll
    for (int t = tid; t < 768; t += 128) {
        const int k = t / 24, c = t - k * 24;
        const int d = c >> 3, f = c & 7;
        const float r = Xs[k][64 + d];
        const float a = r * (float)(1 << (f & 3));
        Xs[k][67 + c] = (f < 4) ? sinf(a) : cosf(a);
    }
    __syncthreads();

    // build A-fragments for GEMM1 (per consumer lane)
    #pragma unroll
    for (int t = tid; t < 384; t += 128) {
        const int ln = t & 31, mt = (t >> 5) & 1, kt = t >> 6;
        const int gg = ln >> 2, tq2 = (ln & 3) * 2;
        const int r = mt * 16 + gg, k0 = kt * 16 + tq2;
        const float2 p0 = *(const float2*)&Xs[r][k0];
        const float2 p1 = *(const float2*)&Xs[r + 8][k0];
        const float2 p2 = *(const float2*)&Xs[r][k0 + 8];
        const float2 p3 = *(const float2*)&Xs[r + 8][k0 + 8];
        uint4 hi, lo;
        split2(p0.x, p0.y, hi.x, lo.x);
        split2(p1.x, p1.y, hi.y, lo.y);
        split2(p2.x, p2.y, hi.z, lo.z);
        split2(p3.x, p3.y, hi.w, lo.w);
        const size_t idx = ((size_t)bs * 12 + kt * 2 + mt) * 32 + ln;
        XfragHi[idx] = hi;
        XfragLo[idx] = lo;
    }
}

struct SmemB {
    uint4 Hfrag[16][2][32][2];   // [kt][mt][lane][{hi,lo}], 32 KB
    uint4 Bbuf[4][2][4][32];     // [warp][buf][nt4][lane], 16 KB
    float rp1[4][32];
    float rp2[4][32];
};

// ---- kernel B: MMA + LN + GELU + max; barrier-free per-warp B staging ----
__global__ __launch_bounds__(128, 4)
void mlp_kernel(const float* __restrict__ b1, const float* __restrict__ g1,
                const float* __restrict__ be1,
                const float* __restrict__ b2, const float* __restrict__ g2,
                const float* __restrict__ be2,
                float* __restrict__ out)
{
    extern __shared__ char rawsm[];
    SmemB* sm = (SmemB*)rawsm;

    const int bs   = blockIdx.x;
    const int tid  = threadIdx.x;
    const int w    = tid >> 5;
    const int lane = tid & 31;
    const int g    = lane >> 2;
    const int tq   = lane & 3;

    float acc[2][8][4];
    const int ncol0 = w * 64 + tq * 2;

    // lane's staging slot: Bbuf[w][st][nt4][lane]
    const uint32_t bufB = smem_u32(&sm->Bbuf[w][0][0][lane]);
    #define STAGEQ(W, kt, q, st) do { \
        const uint4* _s = (W) + (kt) * 1024 + w * 256 + (q) * 128 + lane; \
        const uint32_t _d = bufB + (unsigned)(st) * 2048; \
        cp16(_d,        _s);       \
        cp16(_d + 512,  _s + 32);  \
        cp16(_d + 1024, _s + 64);  \
        cp16(_d + 1536, _s + 96);  \
        CP_COMMIT(); \
    } while (0)

    // kick off the very first quad ASAP
    STAGEQ(W1frag, 0, 0, 0);

    // ---- GEMM1: staged B, A-frags prefetched from global. ----
    {
        #pragma unroll
        for (int nt = 0; nt < 8; ++nt) {
            const float2 bp = *(const float2*)&b1[ncol0 + nt * 8];
            acc[0][nt][0] = bp.x; acc[0][nt][1] = bp.y;
            acc[0][nt][2] = bp.x; acc[0][nt][3] = bp.y;
            acc[1][nt][0] = bp.x; acc[1][nt][1] = bp.y;
            acc[1][nt][2] = bp.x; acc[1][nt][3] = bp.y;
        }
        const size_t base = (size_t)bs * 12 * 32 + lane;
        uint4 Ah0 = XfragHi[base], Al0 = XfragLo[base];
        uint4 Ah1 = XfragHi[base + 32], Al1 = XfragLo[base + 32];
        int st = 0;
        #pragma unroll
        for (int kt = 0; kt < 6; ++kt) {
            uint4 Nh0, Nl0, Nh1, Nl1;
            if (kt < 5) {
                const size_t nb = base + (kt + 1) * 64;
                Nh0 = XfragHi[nb];      Nl0 = XfragLo[nb];
                Nh1 = XfragHi[nb + 32]; Nl1 = XfragLo[nb + 32];
            }
            #pragma unroll
            for (int q = 0; q < 2; ++q) {
                if (kt == 5 && q == 1) {
                    STAGEQ(W2frag, 0, 0, st ^ 1);   // pipeline into GEMM2
                } else if (q == 0) {
                    STAGEQ(W1frag, kt, 1, st ^ 1);
                } else {
                    STAGEQ(W1frag, kt + 1, 0, st ^ 1);
                }
                CP_WAIT1();                          // buffer st ready (self-staged)
                const uint4* Bq = &sm->Bbuf[w][st][0][lane];
                #pragma unroll
                for (int nt4 = 0; nt4 < 4; ++nt4) {
                    const uint4 B = Bq[nt4 * 32];
                    const int nt = q * 4 + nt4;
                    mma16816(acc[0][nt], &Ah0.x, B.x, B.y);
                    mma16816(acc[0][nt], &Ah0.x, B.z, B.w);
                    mma16816(acc[0][nt], &Al0.x, B.x, B.y);
                    mma16816(acc[1][nt], &Ah1.x, B.x, B.y);
                    mma16816(acc[1][nt], &Ah1.x, B.z, B.w);
                    mma16816(acc[1][nt], &Al1.x, B.x, B.y);
                }
                st ^= 1;
            }
            if (kt < 5) { Ah0 = Nh0; Al0 = Nl0; Ah1 = Nh1; Al1 = Nl1; }
        }
    }
    // NOTE: GEMM2's quad (0,0) is in flight in buffer 0; epilogue overlaps it.

    float mu[2][2], rs[2][2];

    // ---- LN1 stats. ----
    {
        float s[2][2];
        #pragma unroll
        for (int mt = 0; mt < 2; ++mt)
            #pragma unroll
            for (int rh = 0; rh < 2; ++rh) {
                float v = 0.f;
                #pragma unroll
                for (int nt = 0; nt < 8; ++nt)
                    v += acc[mt][nt][2 * rh] + acc[mt][nt][2 * rh + 1];
                s[mt][rh] = v;
            }
        #pragma unroll
        for (int o = 1; o <= 2; o <<= 1)
            #pragma unroll
            for (int mt = 0; mt < 2; ++mt)
                #pragma unroll
                for (int rh = 0; rh < 2; ++rh)
                    s[mt][rh] += __shfl_xor_sync(0xffffffffu, s[mt][rh], o);
        if (tq == 0)
            #pragma unroll
            for (int mt = 0; mt < 2; ++mt)
                #pragma unroll
                for (int rh = 0; rh < 2; ++rh)
                    sm->rp1[w][mt * 16 + rh * 8 + g] = s[mt][rh];
        __syncthreads();
        #pragma unroll
        for (int mt = 0; mt < 2; ++mt)
            #pragma unroll
            for (int rh = 0; rh < 2; ++rh) {
                const int row = mt * 16 + rh * 8 + g;
                mu[mt][rh] = (sm->rp1[0][row] + sm->rp1[1][row] +
                              sm->rp1[2][row] + sm->rp1[3][row]) * (1.0f / 256.0f);
            }
        float vs[2][2];
        #pragma unroll
        for (int mt = 0; mt < 2; ++mt)
            #pragma unroll
            for (int rh = 0; rh < 2; ++rh) {
                float v = 0.f;
                #pragma unroll
                for (int nt = 0; nt < 8; ++nt) {
                    const float d0 = acc[mt][nt][2 * rh]     - mu[mt][rh];
                    const float d1 = acc[mt][nt][2 * rh + 1] - mu[mt][rh];
                    v = fmaf(d0, d0, fmaf(d1, d1, v));
                }
                vs[mt][rh] = v;
            }
        #pragma unroll
        for (int o = 1; o <= 2; o <<= 1)
            #pragma unroll
            for (int mt = 0; mt < 2; ++mt)
                #pragma unroll
                for (int rh = 0; rh < 2; ++rh)
                    vs[mt][rh] += __shfl_xor_sync(0xffffffffu, vs[mt][rh], o);
        if (tq == 0)
            #pragma unroll
            for (int mt = 0; mt < 2; ++mt)
                #pragma unroll
                for (int rh = 0; rh < 2; ++rh)
                    sm->rp2[w][mt * 16 + rh * 8 + g] = vs[mt][rh];
        __syncthreads();
        #pragma unroll
        for (int mt = 0; mt < 2; ++mt)
            #pragma unroll
            for (int rh = 0; rh < 2; ++rh) {
                const int row = mt * 16 + rh * 8 + g;
                rs[mt][rh] = rsqrtf((sm->rp2[0][row] + sm->rp2[1][row] +
                                     sm->rp2[2][row] + sm->rp2[3][row]) * (1.0f / 256.0f)
                                    + 1e-5f);
            }
    }

    // ---- LN1 apply + fast GELU, pack to Hfrag. ----
    {
        #pragma unroll
        for (int mt = 0; mt < 2; ++mt)
            #pragma unroll
            for (int j = 0; j < 4; ++j) {
                float u[2][4];
                #pragma unroll
                for (int q2 = 0; q2 < 2; ++q2) {
                    const int nt = 2 * j + q2;
                    const float2 gp = *(const float2*)&g1[ncol0 + nt * 8];
                    const float2 ep = *(const float2*)&be1[ncol0 + nt * 8];
                    #pragma unroll
                    for (int q = 0; q < 4; ++q) {
                        const int rh = q >> 1, e = q & 1;
                        const float gg = e ? gp.y : gp.x;
                        const float ee = e ? ep.y : ep.x;
                        const float t = (acc[mt][nt][q] - mu[mt][rh]) * rs[mt][rh] * gg + ee;
                        u[q2][q] = gelu(t);
                    }
                }
                uint4 hi, lo;
                split2(u[0][0], u[0][1], hi.x, lo.x);
                split2(u[0][2], u[0][3], hi.y, lo.y);
                split2(u[1][0], u[1][1], hi.z, lo.z);
                split2(u[1][2], u[1][3], hi.w, lo.w);
                sm->Hfrag[w * 4 + j][mt][lane][0] = hi;
                sm->Hfrag[w * 4 + j][mt][lane][1] = lo;
            }
    }
    __syncthreads();

    // ---- GEMM2: staged B double-buffered by nt-quad, no barriers. ----
    {
        #pragma unroll
        for (int nt = 0; nt < 8; ++nt) {
            const float2 bp = *(const float2*)&b2[ncol0 + nt * 8];
            acc[0][nt][0] = bp.x; acc[0][nt][1] = bp.y;
            acc[0][nt][2] = bp.x; acc[0][nt][3] = bp.y;
            acc[1][nt][0] = bp.x; acc[1][nt][1] = bp.y;
            acc[1][nt][2] = bp.x; acc[1][nt][3] = bp.y;
        }
        int st = 0;   // GEMM1's pipeline parity: quad (0,0) sits in buffer 0
        #pragma unroll 2
        for (int kt = 0; kt < 16; ++kt) {
            const uint4 Ahi0 = sm->Hfrag[kt][0][lane][0];
            const uint4 Alo0 = sm->Hfrag[kt][0][lane][1];
            const uint4 Ahi1 = sm->Hfrag[kt][1][lane][0];
            const uint4 Alo1 = sm->Hfrag[kt][1][lane][1];
            #pragma unroll
            for (int q = 0; q < 2; ++q) {
                if (kt == 15 && q == 1) {
                    CP_WAIT0();
                } else {
                    if (q == 0) STAGEQ(W2frag, kt, 1, st ^ 1);
                    else        STAGEQ(W2frag, kt + 1, 0, st ^ 1);
                    CP_WAIT1();
                }
                const uint4* Bq = &sm->Bbuf[w][st][0][lane];
                #pragma unroll
                for (int nt4 = 0; nt4 < 4; ++nt4) {
                    const uint4 B = Bq[nt4 * 32];
                    const int nt = q * 4 + nt4;
                    mma16816(acc[0][nt], &Ahi0.x, B.x, B.y);
                    mma16816(acc[0][nt], &Ahi0.x, B.z, B.w);
                    mma16816(acc[0][nt], &Alo0.x, B.x, B.y);
                    mma16816(acc[1][nt], &Ahi1.x, B.x, B.y);
                    mma16816(acc[1][nt], &Ahi1.x, B.z, B.w);
                    mma16816(acc[1][nt], &Alo1.x, B.x, B.y);
                }
                st ^= 1;
            }
        }
    }

    // ---- LN2 stats. ----
    {
        float s[2][2];
        #pragma unroll
        for (int mt = 0; mt < 2; ++mt)
            #pragma unroll
            for (int rh = 0; rh < 2; ++rh) {
                float v = 0.f;
                #pragma unroll
                for (int nt = 0; nt < 8; ++nt)
                    v += acc[mt][nt][2 * rh] + acc[mt][nt][2 * rh + 1];
                s[mt][rh] = v;
            }
        #pragma unroll
        for (int o = 1; o <= 2; o <<= 1)
            #pragma unroll
            for (int mt = 0; mt < 2; ++mt)
                #pragma unroll
                for (int rh = 0; rh < 2; ++rh)
                    s[mt][rh] += __shfl_xor_sync(0xffffffffu, s[mt][rh], o);
        if (tq == 0)
            #pragma unroll
            for (int mt = 0; mt < 2; ++mt)
                #pragma unroll
                for (int rh = 0; rh < 2; ++rh)
                    sm->rp1[w][mt * 16 + rh * 8 + g] = s[mt][rh];
        __syncthreads();
        #pragma unroll
        for (int mt = 0; mt < 2; ++mt)
            #pragma unroll
            for (int rh = 0; rh < 2; ++rh) {
                const int row = mt * 16 + rh * 8 + g;
                mu[mt][rh] = (sm->rp1[0][row] + sm->rp1[1][row] +
                              sm->rp1[2][row] + sm->rp1[3][row]) * (1.0f / 256.0f);
            }
        float vs[2][2];
        #pragma unroll
        for (int mt = 0; mt < 2; ++mt)
            #pragma unroll
            for (int rh = 0; rh < 2; ++rh) {
                float v = 0.f;
                #pragma unroll
                for (int nt = 0; nt < 8; ++nt) {
                    const float d0 = acc[mt][nt][2 * rh]     - mu[mt][rh];
                    const float d1 = acc[mt][nt][2 * rh + 1] - mu[mt][rh];
                    v = fmaf(d0, d0, fmaf(d1, d1, v));
                }
                vs[mt][rh] = v;
            }
        #pragma unroll
        for (int o = 1; o <= 2; o <<= 1)
            #pragma unroll
            for (int mt = 0; mt < 2; ++mt)
                #pragma unroll
                for (int rh = 0; rh < 2; ++rh)
                    vs[mt][rh] += __shfl_xor_sync(0xffffffffu, vs[mt][rh], o);
        if (tq == 0)
            #pragma unroll
            for (int mt = 0; mt < 2; ++mt)
                #pragma unroll
                for (int rh = 0; rh < 2; ++rh)
                    sm->rp2[w][mt * 16 + rh * 8 + g] = vs[mt][rh];
        __syncthreads();
        #pragma unroll
        for (int mt = 0; mt < 2; ++mt)
            #pragma unroll
            for (int rh = 0; rh < 2; ++rh) {
                const int row = mt * 16 + rh * 8 + g;
                rs[mt][rh] = rsqrtf((sm->rp2[0][row] + sm->rp2[1][row] +
                                     sm->rp2[2][row] + sm->rp2[3][row]) * (1.0f / 256.0f)
                                    + 1e-5f);
            }
    }

    // ---- LN2 apply + max over 32 rows per column. ----
    {
        #pragma unroll
        for (int nt = 0; nt < 8; ++nt) {
            const float2 gp = *(const float2*)&g2[ncol0 + nt * 8];
            const float2 ep = *(const float2*)&be2[ncol0 + nt * 8];
            float m0 = -3.402823466e38f, m1 = m0;
            #pragma unroll
            for (int mt = 0; mt < 2; ++mt)
                #pragma unroll
                for (int rh = 0; rh < 2; ++rh) {
                    m0 = fmaxf(m0, (acc[mt][nt][2 * rh]     - mu[mt][rh]) * rs[mt][rh] * gp.x + ep.x);
                    m1 = fmaxf(m1, (acc[mt][nt][2 * rh + 1] - mu[mt][rh]) * rs[mt][rh] * gp.y + ep.y);
                }
            #pragma unroll
            for (int o = 4; o <= 16; o <<= 1) {
                m0 = fmaxf(m0, __shfl_xor_sync(0xffffffffu, m0, o));
                m1 = fmaxf(m1, __shfl_xor_sync(0xffffffffu, m1, o));
            }
            if (lane < 4) {
                out[(size_t)bs * PC + ncol0 + nt * 8]     = m0;
                out[(size_t)bs * PC + ncol0 + nt * 8 + 1] = m1;
            }
        }
    }
    #undef STAGEQ
}

extern "C" void kernel_launch(void* const* d_in, const int* in_sizes, int n_in,
                              void* d_out, int out_size) {
    const float* xyz    = (const float*)d_in[0];
    const float* feat   = (const float*)d_in[1];
    const float* center = (const float*)d_in[2];
    const float* W1     = (const float*)d_in[3];
    const float* b1     = (const float*)d_in[4];
    const float* g1     = (const float*)d_in[5];
    const float* be1    = (const float*)d_in[6];
    const float* W2     = (const float*)d_in[7];
    const float* b2     = (const float*)d_in[8];
    const float* g2     = (const float*)d_in[9];
    const float* be2    = (const float*)d_in[10];
    float* out = (float*)d_out;

    prep_kernel<<<(6144 + 16384 + 255) / 256, 256>>>(W1, W2);
    group_kernel<<<NPATCH, 128>>>(xyz, feat, center, out);

    cudaFuncSetAttribute(mlp_kernel, cudaFuncAttributeMaxDynamicSharedMemorySize,
                         (int)sizeof(SmemB));
    mlp_kernel<<<NPATCH, 128, sizeof(SmemB)>>>(b1, g1, be1, b2, g2, be2, out);
}

// round 17
// speedup vs baseline: 1.1344x; 1.1344x over previous
#include <cuda_runtime.h>
#include <math.h>
#include <stdint.h>

#define NB 8
#define NPTS 16384
#define NS 1024
#define PC 256
#define R2 0.0625f
#define NPATCH (NB * NS)

// ---- precomputed W fragments (B-operand layout for mma.m16n8k16) ----
// index = (kt*32 + nt)*32 + lane ; {x,y,z,w} = {b0hi, b1hi, b0lo, b1lo}
__device__ uint4 W1frag[6 * 32 * 32];     // K padded 91 -> 96
__device__ uint4 W2frag[16 * 32 * 32];
// ---- precomputed X A-fragments: [patch][kt(6)][mt(2)][lane(32)] ----
__device__ uint4 XfragHi[(size_t)NPATCH * 12 * 32];
__device__ uint4 XfragLo[(size_t)NPATCH * 12 * 32];

__device__ __forceinline__ unsigned pack_bf16(float e0, float e1) {
    unsigned r;
    asm("cvt.rn.bf16x2.f32 %0, %1, %2;" : "=r"(r) : "f"(e1), "f"(e0));
    return r;   // low half = bf16(e0), high half = bf16(e1)
}
__device__ __forceinline__ void split2(float e0, float e1, unsigned &hi, unsigned &lo) {
    hi = pack_bf16(e0, e1);
    const float h0 = __uint_as_float(hi << 16);
    const float h1 = __uint_as_float(hi & 0xffff0000u);
    lo = pack_bf16(e0 - h0, e1 - h1);
}
__device__ __forceinline__ void mma16816(float* c, const unsigned* a,
                                         unsigned b0, unsigned b1) {
    asm("mma.sync.aligned.m16n8k16.row.col.f32.bf16.bf16.f32 "
        "{%0,%1,%2,%3}, {%4,%5,%6,%7}, {%8,%9}, {%0,%1,%2,%3};"
        : "+f"(c[0]), "+f"(c[1]), "+f"(c[2]), "+f"(c[3])
        : "r"(a[0]), "r"(a[1]), "r"(a[2]), "r"(a[3]), "r"(b0), "r"(b1));
}

// Abramowitz-Stegun 7.1.26 rational erf: |err| <= 1.5e-7, branch-free.
__device__ __forceinline__ float fast_erff(float x) {
    const float ax = fabsf(x);
    const float t = __fdividef(1.0f, fmaf(0.3275911f, ax, 1.0f));
    float p = fmaf(1.061405429f, t, -1.453152027f);
    p = fmaf(p, t, 1.421413741f);
    p = fmaf(p, t, -0.284496736f);
    p = fmaf(p, t, 0.254829592f);
    p *= t;
    const float e = __expf(-ax * ax);
    const float r = fmaf(-p, e, 1.0f);
    return copysignf(r, x);
}
__device__ __forceinline__ float gelu(float v) {
    return 0.5f * v * (1.0f + fast_erff(v * 0.70710678118654752440f));
}

// ---- prep: build W fragments (idempotent each launch) ----
__global__ void prep_kernel(const float* __restrict__ W1, const float* __restrict__ W2) {
    const int t = blockIdx.x * blockDim.x + threadIdx.x;
    if (t < 6144) {
        const int lane = t & 31, nt = (t >> 5) & 31, kt = t >> 10;
        const int k0 = kt * 16 + (lane & 3) * 2;
        const int n  = nt * 8 + (lane >> 2);
        const float e00 = (k0     < 91) ? W1[(k0    ) * PC + n] : 0.f;
        const float e01 = (k0 + 1 < 91) ? W1[(k0 + 1) * PC + n] : 0.f;
        const float e10 = (k0 + 8 < 91) ? W1[(k0 + 8) * PC + n] : 0.f;
        const float e11 = (k0 + 9 < 91) ? W1[(k0 + 9) * PC + n] : 0.f;
        uint4 v;
        split2(e00, e01, v.x, v.z);
        split2(e10, e11, v.y, v.w);
        W1frag[t] = v;
    } else if (t < 6144 + 16384) {
        const int u = t - 6144;
        const int lane = u & 31, nt = (u >> 5) & 31, kt = u >> 10;
        const int k0 = kt * 16 + (lane & 3) * 2;
        const int n  = nt * 8 + (lane >> 2);
        uint4 v;
        split2(W2[k0 * PC + n],       W2[(k0 + 1) * PC + n], v.x, v.z);
        split2(W2[(k0 + 8) * PC + n], W2[(k0 + 9) * PC + n], v.y, v.w);
        W2frag[u] = v;
    }
}

// ---- kernel A: ball query + gather + encode + A-fragment build ----
__global__ __launch_bounds__(128)
void group_kernel(const float* __restrict__ xyz, const float* __restrict__ feat,
                  const float* __restrict__ center, float* __restrict__ out)
{
    __shared__ float Xs[32][98];
    __shared__ int sc_idx[4][32];
    __shared__ int sc_cnt[4];
    __shared__ int gidx[32];

    const int bs   = blockIdx.x;
    const int b    = bs >> 10;
    const int tid  = threadIdx.x;
    const int w    = tid >> 5;
    const int lane = tid & 31;

    const float cx = center[bs * 3 + 0];
    const float cy = center[bs * 3 + 1];
    const float cz = center[bs * 3 + 2];
    const float cs = __fadd_rn(__fadd_rn(__fmul_rn(cx, cx), __fmul_rn(cy, cy)),
                               __fmul_rn(cz, cz));

    // ball query: 4 warps x 4096-point segments, first-32 kept
    {
        const float* xb = xyz + (size_t)b * NPTS * 3;
        int cnt = 0;
        const int base = w * 4096;
        for (int it = 0; it < 128; ++it) {
            const int n = base + it * 32 + lane;
            const float px = xb[n * 3 + 0];
            const float py = xb[n * 3 + 1];
            const float pz = xb[n * 3 + 2];
            const float ps = __fadd_rn(__fadd_rn(__fmul_rn(px, px), __fmul_rn(py, py)),
                                       __fmul_rn(pz, pz));
            const float dt = __fadd_rn(__fadd_rn(__fmul_rn(cx, px), __fmul_rn(cy, py)),
                                       __fmul_rn(cz, pz));
            const float sq = __fsub_rn(__fadd_rn(cs, ps), __fmul_rn(2.0f, dt));
            const bool hit = (sq <= R2);
            const unsigned m = __ballot_sync(0xffffffffu, hit);
            const int rank = __popc(m & ((1u << lane) - 1u));
            if (hit && (cnt + rank) < 32) sc_idx[w][cnt + rank] = n;
            cnt += __popc(m);
            if (cnt >= 32) break;
        }
        if (lane == 0) sc_cnt[w] = cnt < 32 ? cnt : 32;
    }
    __syncthreads();

    if (w == 0) {
        int val = NPTS, tot = 0;
        #pragma unroll
        for (int ww = 0; ww < 4; ++ww) {
            const int c = sc_cnt[ww];
            if (lane >= tot && lane < tot + c) val = sc_idx[ww][lane - tot];
            tot += c;
        }
        const int v0 = __shfl_sync(0xffffffffu, val, 0);
        if (val == NPTS) val = v0;
        gidx[lane] = val < (NPTS - 1) ? val : (NPTS - 1);
        out[(size_t)NPATCH * PC + (size_t)bs * 32 + lane] = (float)val;
    }
    __syncthreads();

    // gather + rel-pos encoding
    if (tid < 96) {
        const int k = tid / 3, d = tid - k * 3;
        const int gi = gidx[k];
        const float cd = (d == 0) ? cx : ((d == 1) ? cy : cz);
        Xs[k][64 + d] = xyz[((size_t)b * NPTS + gi) * 3 + d] - cd;
    }
    #pragma unroll
    for (int t = tid; t < 512; t += 128) {
        const int k = t >> 4, c = (t & 15) * 4;
        const float4 v = *(const float4*)&feat[((size_t)b * NPTS + gidx[k]) * 64 + c];
        Xs[k][c + 0] = v.x; Xs[k][c + 1] = v.y;
        Xs[k][c + 2] = v.z; Xs[k][c + 3] = v.w;
    }
    #pragma unroll
    for (int t = tid; t < 32 * 7; t += 128) {
        Xs[t / 7][91 + t % 7] = 0.f;
    }
    __syncthreads();
    #pragma unroll
    for (int t = tid; t < 768; t += 128) {
        const int k = t / 24, c = t - k * 24;
        const int d = c >> 3, f = c & 7;
        const float r = Xs[k][64 + d];
        const float a = r * (float)(1 << (f & 3));
        Xs[k][67 + c] = (f < 4) ? sinf(a) : cosf(a);
    }
    __syncthreads();

    // build A-fragments for GEMM1 (per consumer lane)
    #pragma unroll
    for (int t = tid; t < 384; t += 128) {
        const int ln = t & 31, mt = (t >> 5) & 1, kt = t >> 6;
        const int gg = ln >> 2, tq2 = (ln & 3) * 2;
        const int r = mt * 16 + gg, k0 = kt * 16 + tq2;
        const float2 p0 = *(const float2*)&Xs[r][k0];
        const float2 p1 = *(const float2*)&Xs[r + 8][k0];
        const float2 p2 = *(const float2*)&Xs[r][k0 + 8];
        const float2 p3 = *(const float2*)&Xs[r + 8][k0 + 8];
        uint4 hi, lo;
        split2(p0.x, p0.y, hi.x, lo.x);
        split2(p1.x, p1.y, hi.y, lo.y);
        split2(p2.x, p2.y, hi.z, lo.z);
        split2(p3.x, p3.y, hi.w, lo.w);
        const size_t idx = ((size_t)bs * 12 + kt * 2 + mt) * 32 + ln;
        XfragHi[idx] = hi;
        XfragLo[idx] = lo;
    }
}

struct SmemB {
    uint4 Hfrag[16][2][32][2];   // [kt][mt][lane][{hi,lo}], 32 KB
    float rp1[4][32];
    float rp2[4][32];
};

// ---- kernel B: MMA + LN + GELU + max; term-major MMA interleave ----
__global__ __launch_bounds__(128, 4)
void mlp_kernel(const float* __restrict__ b1, const float* __restrict__ g1,
                const float* __restrict__ be1,
                const float* __restrict__ b2, const float* __restrict__ g2,
                const float* __restrict__ be2,
                float* __restrict__ out)
{
    extern __shared__ char rawsm[];
    SmemB* sm = (SmemB*)rawsm;

    const int bs   = blockIdx.x;
    const int tid  = threadIdx.x;
    const int w    = tid >> 5;
    const int lane = tid & 31;
    const int g    = lane >> 2;
    const int tq   = lane & 3;

    float acc[2][8][4];
    const int ncol0 = w * 64 + tq * 2;

    // One quad (4 nt, 2 m-tiles): three term-passes, each with 8 independent
    // MMAs -> same-accumulator reuse distance is 8 (covers HMMA latency).
    #define QUAD3(Ahi0p, Alo0p, Ahi1p, Alo1p, B0, B1, B2, B3, q) do { \
        mma16816(acc[0][4*(q)+0], Ahi0p, (B0).x, (B0).y); \
        mma16816(acc[1][4*(q)+0], Ahi1p, (B0).x, (B0).y); \
        mma16816(acc[0][4*(q)+1], Ahi0p, (B1).x, (B1).y); \
        mma16816(acc[1][4*(q)+1], Ahi1p, (B1).x, (B1).y); \
        mma16816(acc[0][4*(q)+2], Ahi0p, (B2).x, (B2).y); \
        mma16816(acc[1][4*(q)+2], Ahi1p, (B2).x, (B2).y); \
        mma16816(acc[0][4*(q)+3], Ahi0p, (B3).x, (B3).y); \
        mma16816(acc[1][4*(q)+3], Ahi1p, (B3).x, (B3).y); \
        mma16816(acc[0][4*(q)+0], Ahi0p, (B0).z, (B0).w); \
        mma16816(acc[1][4*(q)+0], Ahi1p, (B0).z, (B0).w); \
        mma16816(acc[0][4*(q)+1], Ahi0p, (B1).z, (B1).w); \
        mma16816(acc[1][4*(q)+1], Ahi1p, (B1).z, (B1).w); \
        mma16816(acc[0][4*(q)+2], Ahi0p, (B2).z, (B2).w); \
        mma16816(acc[1][4*(q)+2], Ahi1p, (B2).z, (B2).w); \
        mma16816(acc[0][4*(q)+3], Ahi0p, (B3).z, (B3).w); \
        mma16816(acc[1][4*(q)+3], Ahi1p, (B3).z, (B3).w); \
        mma16816(acc[0][4*(q)+0], Alo0p, (B0).x, (B0).y); \
        mma16816(acc[1][4*(q)+0], Alo1p, (B0).x, (B0).y); \
        mma16816(acc[0][4*(q)+1], Alo0p, (B1).x, (B1).y); \
        mma16816(acc[1][4*(q)+1], Alo1p, (B1).x, (B1).y); \
        mma16816(acc[0][4*(q)+2], Alo0p, (B2).x, (B2).y); \
        mma16816(acc[1][4*(q)+2], Alo1p, (B2).x, (B2).y); \
        mma16816(acc[0][4*(q)+3], Alo0p, (B3).x, (B3).y); \
        mma16816(acc[1][4*(q)+3], Alo1p, (B3).x, (B3).y); \
    } while (0)

    // ---- GEMM1: A-frags from global (prefetch one kt ahead). ----
    {
        #pragma unroll
        for (int nt = 0; nt < 8; ++nt) {
            const float2 bp = *(const float2*)&b1[ncol0 + nt * 8];
            acc[0][nt][0] = bp.x; acc[0][nt][1] = bp.y;
            acc[0][nt][2] = bp.x; acc[0][nt][3] = bp.y;
            acc[1][nt][0] = bp.x; acc[1][nt][1] = bp.y;
            acc[1][nt][2] = bp.x; acc[1][nt][3] = bp.y;
        }
        const size_t base = (size_t)bs * 12 * 32 + lane;
        uint4 Ah0 = XfragHi[base], Al0 = XfragLo[base];
        uint4 Ah1 = XfragHi[base + 32], Al1 = XfragLo[base + 32];
        #pragma unroll
        for (int kt = 0; kt < 6; ++kt) {
            uint4 Nh0, Nl0, Nh1, Nl1;
            if (kt < 5) {
                const size_t nb = base + (kt + 1) * 64;
                Nh0 = XfragHi[nb];      Nl0 = XfragLo[nb];
                Nh1 = XfragHi[nb + 32]; Nl1 = XfragLo[nb + 32];
            }
            const uint4* Wp = &W1frag[(kt * 32 + w * 8) * 32 + lane];
            #pragma unroll
            for (int q = 0; q < 2; ++q) {
                const uint4 B0 = Wp[(q * 4 + 0) * 32];
                const uint4 B1 = Wp[(q * 4 + 1) * 32];
                const uint4 B2 = Wp[(q * 4 + 2) * 32];
                const uint4 B3 = Wp[(q * 4 + 3) * 32];
                QUAD3(&Ah0.x, &Al0.x, &Ah1.x, &Al1.x, B0, B1, B2, B3, q);
            }
            if (kt < 5) { Ah0 = Nh0; Al0 = Nl0; Ah1 = Nh1; Al1 = Nl1; }
        }
    }

    float mu[2][2], rs[2][2];

    // ---- LN1 stats. ----
    {
        float s[2][2];
        #pragma unroll
        for (int mt = 0; mt < 2; ++mt)
            #pragma unroll
            for (int rh = 0; rh < 2; ++rh) {
                float v = 0.f;
                #pragma unroll
                for (int nt = 0; nt < 8; ++nt)
                    v += acc[mt][nt][2 * rh] + acc[mt][nt][2 * rh + 1];
                s[mt][rh] = v;
            }
        #pragma unroll
        for (int o = 1; o <= 2; o <<= 1)
            #pragma unroll
            for (int mt = 0; mt < 2; ++mt)
                #pragma unroll
                for (int rh = 0; rh < 2; ++rh)
                    s[mt][rh] += __shfl_xor_sync(0xffffffffu, s[mt][rh], o);
        if (tq == 0)
            #pragma unroll
            for (int mt = 0; mt < 2; ++mt)
                #pragma unroll
                for (int rh = 0; rh < 2; ++rh)
                    sm->rp1[w][mt * 16 + rh * 8 + g] = s[mt][rh];
        __syncthreads();
        #pragma unroll
        for (int mt = 0; mt < 2; ++mt)
            #pragma unroll
            for (int rh = 0; rh < 2; ++rh) {
                const int row = mt * 16 + rh * 8 + g;
                mu[mt][rh] = (sm->rp1[0][row] + sm->rp1[1][row] +
                              sm->rp1[2][row] + sm->rp1[3][row]) * (1.0f / 256.0f);
            }
        float vs[2][2];
        #pragma unroll
        for (int mt = 0; mt < 2; ++mt)
            #pragma unroll
            for (int rh = 0; rh < 2; ++rh) {
                float v = 0.f;
                #pragma unroll
                for (int nt = 0; nt < 8; ++nt) {
                    const float d0 = acc[mt][nt][2 * rh]     - mu[mt][rh];
                    const float d1 = acc[mt][nt][2 * rh + 1] - mu[mt][rh];
                    v = fmaf(d0, d0, fmaf(d1, d1, v));
                }
                vs[mt][rh] = v;
            }
        #pragma unroll
        for (int o = 1; o <= 2; o <<= 1)
            #pragma unroll
            for (int mt = 0; mt < 2; ++mt)
                #pragma unroll
                for (int rh = 0; rh < 2; ++rh)
                    vs[mt][rh] += __shfl_xor_sync(0xffffffffu, vs[mt][rh], o);
        if (tq == 0)
            #pragma unroll
            for (int mt = 0; mt < 2; ++mt)
                #pragma unroll
                for (int rh = 0; rh < 2; ++rh)
                    sm->rp2[w][mt * 16 + rh * 8 + g] = vs[mt][rh];
        __syncthreads();
        #pragma unroll
        for (int mt = 0; mt < 2; ++mt)
            #pragma unroll
            for (int rh = 0; rh < 2; ++rh) {
                const int row = mt * 16 + rh * 8 + g;
                rs[mt][rh] = rsqrtf((sm->rp2[0][row] + sm->rp2[1][row] +
                                     sm->rp2[2][row] + sm->rp2[3][row]) * (1.0f / 256.0f)
                                    + 1e-5f);
            }
    }

    // ---- LN1 apply + fast GELU, pack to Hfrag. ----
    {
        #pragma unroll
        for (int mt = 0; mt < 2; ++mt)
            #pragma unroll
            for (int j = 0; j < 4; ++j) {
                float u[2][4];
                #pragma unroll
                for (int q2 = 0; q2 < 2; ++q2) {
                    const int nt = 2 * j + q2;
                    const float2 gp = *(const float2*)&g1[ncol0 + nt * 8];
                    const float2 ep = *(const float2*)&be1[ncol0 + nt * 8];
                    #pragma unroll
                    for (int q = 0; q < 4; ++q) {
                        const int rh = q >> 1, e = q & 1;
                        const float gg = e ? gp.y : gp.x;
                        const float ee = e ? ep.y : ep.x;
                        const float t = (acc[mt][nt][q] - mu[mt][rh]) * rs[mt][rh] * gg + ee;
                        u[q2][q] = gelu(t);
                    }
                }
                uint4 hi, lo;
                split2(u[0][0], u[0][1], hi.x, lo.x);
                split2(u[0][2], u[0][3], hi.y, lo.y);
                split2(u[1][0], u[1][1], hi.z, lo.z);
                split2(u[1][2], u[1][3], hi.w, lo.w);
                sm->Hfrag[w * 4 + j][mt][lane][0] = hi;
                sm->Hfrag[w * 4 + j][mt][lane][1] = lo;
            }
    }
    __syncthreads();

    // ---- GEMM2: term-major interleave, B from global LDG. ----
    {
        #pragma unroll
        for (int nt = 0; nt < 8; ++nt) {
            const float2 bp = *(const float2*)&b2[ncol0 + nt * 8];
            acc[0][nt][0] = bp.x; acc[0][nt][1] = bp.y;
            acc[0][nt][2] = bp.x; acc[0][nt][3] = bp.y;
            acc[1][nt][0] = bp.x; acc[1][nt][1] = bp.y;
            acc[1][nt][2] = bp.x; acc[1][nt][3] = bp.y;
        }
        #pragma unroll 2
        for (int kt = 0; kt < 16; ++kt) {
            const uint4 Ahi0 = sm->Hfrag[kt][0][lane][0];
            const uint4 Alo0 = sm->Hfrag[kt][0][lane][1];
            const uint4 Ahi1 = sm->Hfrag[kt][1][lane][0];
            const uint4 Alo1 = sm->Hfrag[kt][1][lane][1];
            const uint4* Wp = &W2frag[(kt * 32 + w * 8) * 32 + lane];
            #pragma unroll
            for (int q = 0; q < 2; ++q) {
                const uint4 B0 = Wp[(q * 4 + 0) * 32];
                const uint4 B1 = Wp[(q * 4 + 1) * 32];
                const uint4 B2 = Wp[(q * 4 + 2) * 32];
                const uint4 B3 = Wp[(q * 4 + 3) * 32];
                QUAD3(&Ahi0.x, &Alo0.x, &Ahi1.x, &Alo1.x, B0, B1, B2, B3, q);
            }
        }
    }
    #undef QUAD3

    // ---- LN2 stats. ----
    {
        float s[2][2];
        #pragma unroll
        for (int mt = 0; mt < 2; ++mt)
            #pragma unroll
            for (int rh = 0; rh < 2; ++rh) {
                float v = 0.f;
                #pragma unroll
                for (int nt = 0; nt < 8; ++nt)
                    v += acc[mt][nt][2 * rh] + acc[mt][nt][2 * rh + 1];
                s[mt][rh] = v;
            }
        #pragma unroll
        for (int o = 1; o <= 2; o <<= 1)
            #pragma unroll
            for (int mt = 0; mt < 2; ++mt)
                #pragma unroll
                for (int rh = 0; rh < 2; ++rh)
                    s[mt][rh] += __shfl_xor_sync(0xffffffffu, s[mt][rh], o);
        if (tq == 0)
            #pragma unroll
            for (int mt = 0; mt < 2; ++mt)
                #pragma unroll
                for (int rh = 0; rh < 2; ++rh)
                    sm->rp1[w][mt * 16 + rh * 8 + g] = s[mt][rh];
        __syncthreads();
        #pragma unroll
        for (int mt = 0; mt < 2; ++mt)
            #pragma unroll
            for (int rh = 0; rh < 2; ++rh) {
                const int row = mt * 16 + rh * 8 + g;
                mu[mt][rh] = (sm->rp1[0][row] + sm->rp1[1][row] +
                              sm->rp1[2][row] + sm->rp1[3][row]) * (1.0f / 256.0f);
            }
        float vs[2][2];
        #pragma unroll
        for (int mt = 0; mt < 2; ++mt)
            #pragma unroll
            for (int rh = 0; rh < 2; ++rh) {
                float v = 0.f;
                #pragma unroll
                for (int nt = 0; nt < 8; ++nt) {
                    const float d0 = acc[mt][nt][2 * rh]     - mu[mt][rh];
                    const float d1 = acc[mt][nt][2 * rh + 1] - mu[mt][rh];
                    v = fmaf(d0, d0, fmaf(d1, d1, v));
                }
                vs[mt][rh] = v;
            }
        #pragma unroll
        for (int o = 1; o <= 2; o <<= 1)
            #pragma unroll
            for (int mt = 0; mt < 2; ++mt)
                #pragma unroll
                for (int rh = 0; rh < 2; ++rh)
                    vs[mt][rh] += __shfl_xor_sync(0xffffffffu, vs[mt][rh], o);
        if (tq == 0)
            #pragma unroll
            for (int mt = 0; mt < 2; ++mt)
                #pragma unroll
                for (int rh = 0; rh < 2; ++rh)
                    sm->rp2[w][mt * 16 + rh * 8 + g] = vs[mt][rh];
        __syncthreads();
        #pragma unroll
        for (int mt = 0; mt < 2; ++mt)
            #pragma unroll
            for (int rh = 0; rh < 2; ++rh) {
                const int row = mt * 16 + rh * 8 + g;
                rs[mt][rh] = rsqrtf((sm->rp2[0][row] + sm->rp2[1][row] +
                                     sm->rp2[2][row] + sm->rp2[3][row]) * (1.0f / 256.0f)
                                    + 1e-5f);
            }
    }

    // ---- LN2 apply + max over 32 rows per column. ----
    {
        #pragma unroll
        for (int nt = 0; nt < 8; ++nt) {
            const float2 gp = *(const float2*)&g2[ncol0 + nt * 8];
            const float2 ep = *(const float2*)&be2[ncol0 + nt * 8];
            float m0 = -3.402823466e38f, m1 = m0;
            #pragma unroll
            for (int mt = 0; mt < 2; ++mt)
                #pragma unroll
                for (int rh = 0; rh < 2; ++rh) {
                    m0 = fmaxf(m0, (acc[mt][nt][2 * rh]     - mu[mt][rh]) * rs[mt][rh] * gp.x + ep.x);
                    m1 = fmaxf(m1, (acc[mt][nt][2 * rh + 1] - mu[mt][rh]) * rs[mt][rh] * gp.y + ep.y);
                }
            #pragma unroll
            for (int o = 4; o <= 16; o <<= 1) {
                m0 = fmaxf(m0, __shfl_xor_sync(0xffffffffu, m0, o));
                m1 = fmaxf(m1, __shfl_xor_sync(0xffffffffu, m1, o));
            }
            if (lane < 4) {
                out[(size_t)bs * PC + ncol0 + nt * 8]     = m0;
                out[(size_t)bs * PC + ncol0 + nt * 8 + 1] = m1;
            }
        }
    }
}

extern "C" void kernel_launch(void* const* d_in, const int* in_sizes, int n_in,
                              void* d_out, int out_size) {
    const float* xyz    = (const float*)d_in[0];
    const float* feat   = (const float*)d_in[1];
    const float* center = (const float*)d_in[2];
    const float* W1     = (const float*)d_in[3];
    const float* b1     = (const float*)d_in[4];
    const float* g1     = (const float*)d_in[5];
    const float* be1    = (const float*)d_in[6];
    const float* W2     = (const float*)d_in[7];
    const float* b2     = (const float*)d_in[8];
    const float* g2     = (const float*)d_in[9];
    const float* be2    = (const float*)d_in[10];
    float* out = (float*)d_out;

    prep_kernel<<<(6144 + 16384 + 255) / 256, 256>>>(W1, W2);
    group_kernel<<<NPATCH, 128>>>(xyz, feat, center, out);

    cudaFuncSetAttribute(mlp_kernel, cudaFuncAttributeMaxDynamicSharedMemorySize,
                         (int)sizeof(SmemB));
    mlp_kernel<<<NPATCH, 128, sizeof(SmemB)>>>(b1, g1, be1, b2, g2, be2, out);
}